// round 2
// baseline (speedup 1.0000x reference)
#include <cuda_runtime.h>
#include <cuda_fp16.h>
#include <cstdint>
#include <cstddef>

#define KDIM 4096
#define NDIM 11008
#define MMAX 8192
#define BM 128
#define BN 128
#define BK 32
#define STAGES 4
#define ROWH (BK + 8)            // padded SMEM row in halfs (40) -> conflict-free ldmatrix
#define TILE_H (BM * ROWH)       // halfs per tile
#define TILE_B (TILE_H * 2)      // bytes per tile (10240)

// Scratch (static device globals — no dynamic allocation allowed)
__device__ __half g_Xh[(size_t)MMAX * KDIM];   // x as fp16, [M, K]
__device__ __half g_Wt[(size_t)NDIM * KDIM];   // dequantized W, transposed: [N, K]

// ---------------- helpers ----------------
__device__ __forceinline__ uint32_t smem_u32(const void* p) {
    uint32_t a;
    asm("{ .reg .u64 t; cvta.to.shared.u64 t, %1; cvt.u32.u64 %0, t; }" : "=r"(a) : "l"(p));
    return a;
}

__device__ __forceinline__ void cp16(uint32_t sdst, const void* gsrc) {
    asm volatile("cp.async.cg.shared.global [%0], [%1], 16;" :: "r"(sdst), "l"(gsrc));
}

__device__ __forceinline__ void ldm_x4(uint32_t& r0, uint32_t& r1, uint32_t& r2, uint32_t& r3,
                                       uint32_t addr) {
    asm volatile("ldmatrix.sync.aligned.m8n8.x4.shared.b16 {%0,%1,%2,%3}, [%4];"
                 : "=r"(r0), "=r"(r1), "=r"(r2), "=r"(r3) : "r"(addr));
}

__device__ __forceinline__ void ldm_x2(uint32_t& r0, uint32_t& r1, uint32_t addr) {
    asm volatile("ldmatrix.sync.aligned.m8n8.x2.shared.b16 {%0,%1}, [%2];"
                 : "=r"(r0), "=r"(r1) : "r"(addr));
}

__device__ __forceinline__ void mma16816(float* c,
                                         uint32_t a0, uint32_t a1, uint32_t a2, uint32_t a3,
                                         uint32_t b0, uint32_t b1) {
    asm volatile("mma.sync.aligned.m16n8k16.row.col.f32.f16.f16.f32 "
                 "{%0,%1,%2,%3}, {%4,%5,%6,%7}, {%8,%9}, {%0,%1,%2,%3};"
                 : "+f"(c[0]), "+f"(c[1]), "+f"(c[2]), "+f"(c[3])
                 : "r"(a0), "r"(a1), "r"(a2), "r"(a3), "r"(b0), "r"(b1));
}

// ---------------- Kernel 1: x fp32 -> fp16 ----------------
__global__ void convert_x_kernel(const float* __restrict__ x, long long n4) {
    long long i = (long long)blockIdx.x * blockDim.x + threadIdx.x;
    if (i < n4) {
        float4 v = reinterpret_cast<const float4*>(x)[i];
        __half2 h0 = __floats2half2_rn(v.x, v.y);
        __half2 h1 = __floats2half2_rn(v.z, v.w);
        reinterpret_cast<__half2*>(g_Xh)[i * 2]     = h0;
        reinterpret_cast<__half2*>(g_Xh)[i * 2 + 1] = h1;
    }
}

// ---------------- Kernel 2: dequant -> Wt[N][K] fp16 ----------------
__global__ void dequant_kernel(const int* __restrict__ qweight,
                               const float* __restrict__ scales,
                               const int* __restrict__ qzeros) {
    int n  = blockIdx.x * blockDim.x + threadIdx.x;   // coalesced along N
    int kp = blockIdx.y;                              // 0..KDIM/8-1
    if (n >= NDIM) return;
    int g = kp >> 4;                                  // (kp*8)/128
    uint32_t qw = (uint32_t)qweight[(size_t)kp * NDIM + n];
    uint32_t zq = ((uint32_t)qzeros[(size_t)g * (NDIM / 8) + (n >> 3)] >> ((n & 7) * 4)) & 15u;
    float z = (float)(zq + 1u);
    float s = scales[(size_t)g * NDIM + n];
    union { uint4 u; __half h[8]; } t;
#pragma unroll
    for (int j = 0; j < 8; ++j) {
        float q = (float)((qw >> (4 * j)) & 15u);
        t.h[j] = __float2half_rn((q - z) * s);
    }
    *reinterpret_cast<uint4*>(&g_Wt[(size_t)n * KDIM + (size_t)kp * 8]) = t.u;
}

// ---------------- Kernel 3: mma.sync fp16 GEMM ----------------
// BM=BN=128, BK=32, 256 threads = 8 warps (2 x 4), warp tile 64x32, 4-stage cp.async.
__global__ void __launch_bounds__(256, 2)
gemm_kernel(const float* __restrict__ bias, float* __restrict__ out) {
    extern __shared__ char dsm[];
    const uint32_t sbase = smem_u32(dsm);

    const int tid  = threadIdx.x;
    const int lane = tid & 31;
    const int wid  = tid >> 5;
    const int warp_m = wid & 1;       // 0..1 -> 64 rows each
    const int warp_n = wid >> 1;      // 0..3 -> 32 cols each
    const int n0 = blockIdx.x * BN;
    const int m0 = blockIdx.y * BM;

    const __half* Ag = g_Xh + (size_t)m0 * KDIM;
    const __half* Bg = g_Wt + (size_t)n0 * KDIM;

    const int lrow = tid >> 2;        // 0..63
    const int lchk = tid & 3;         // 16B chunk within 64B k-row

    float acc[4][4][4];
#pragma unroll
    for (int i = 0; i < 4; ++i)
#pragma unroll
        for (int j = 0; j < 4; ++j)
#pragma unroll
            for (int k = 0; k < 4; ++k) acc[i][j][k] = 0.f;

    // per-thread fragment SMEM coordinates
    const int a_r = warp_m * 64 + (lane & 15);
    const int a_c = (lane >> 4) * 8;
    const int bl  = lane & 15;
    const int b_r = warp_n * 32 + (bl & 7);
    const int b_c = (bl >> 3) * 8;

    const int NIT = KDIM / BK;        // 128

    // prologue: fill STAGES-1 stages
#pragma unroll
    for (int s = 0; s < STAGES - 1; ++s) {
        const int k0 = s * BK;
        uint32_t sa  = sbase + s * TILE_B;
        uint32_t sbb = sbase + STAGES * TILE_B + s * TILE_B;
#pragma unroll
        for (int p = 0; p < 2; ++p) {
            const int row = lrow + p * 64;
            const uint32_t soff = (uint32_t)(row * ROWH + lchk * 8) * 2;
            cp16(sa + soff,  Ag + (size_t)row * KDIM + k0 + lchk * 8);
            cp16(sbb + soff, Bg + (size_t)row * KDIM + k0 + lchk * 8);
        }
        asm volatile("cp.async.commit_group;" ::: "memory");
    }

#pragma unroll 1
    for (int it = 0; it < NIT; ++it) {
        asm volatile("cp.async.wait_group 2;" ::: "memory");
        __syncthreads();

        // issue next stage (overwrites stage computed last iteration — safe after sync)
        const int nk = it + STAGES - 1;
        if (nk < NIT) {
            const int st = nk & (STAGES - 1);
            const int k0 = nk * BK;
            uint32_t sa  = sbase + st * TILE_B;
            uint32_t sbb = sbase + STAGES * TILE_B + st * TILE_B;
#pragma unroll
            for (int p = 0; p < 2; ++p) {
                const int row = lrow + p * 64;
                const uint32_t soff = (uint32_t)(row * ROWH + lchk * 8) * 2;
                cp16(sa + soff,  Ag + (size_t)row * KDIM + k0 + lchk * 8);
                cp16(sbb + soff, Bg + (size_t)row * KDIM + k0 + lchk * 8);
            }
        }
        asm volatile("cp.async.commit_group;" ::: "memory");

        // compute current stage
        const int st = it & (STAGES - 1);
        const uint32_t sa  = sbase + st * TILE_B;
        const uint32_t sbb = sbase + STAGES * TILE_B + st * TILE_B;
#pragma unroll
        for (int ks = 0; ks < 2; ++ks) {
            uint32_t Af[4][4], Bf[4][2];
#pragma unroll
            for (int mi = 0; mi < 4; ++mi)
                ldm_x4(Af[mi][0], Af[mi][1], Af[mi][2], Af[mi][3],
                       sa + (uint32_t)(((a_r + mi * 16) * ROWH) + ks * 16 + a_c) * 2);
#pragma unroll
            for (int ni = 0; ni < 4; ++ni)
                ldm_x2(Bf[ni][0], Bf[ni][1],
                       sbb + (uint32_t)(((b_r + ni * 8) * ROWH) + ks * 16 + b_c) * 2);
#pragma unroll
            for (int mi = 0; mi < 4; ++mi)
#pragma unroll
                for (int ni = 0; ni < 4; ++ni)
                    mma16816(acc[mi][ni],
                             Af[mi][0], Af[mi][1], Af[mi][2], Af[mi][3],
                             Bf[ni][0], Bf[ni][1]);
        }
    }
    asm volatile("cp.async.wait_group 0;" ::: "memory");

    // epilogue: c0,c1 -> (row = lane>>2, cols = (lane&3)*2 +0/1); c2,c3 -> row+8
    const int r  = lane >> 2;
    const int c2 = (lane & 3) * 2;
    const int orow0 = m0 + warp_m * 64;
    const int ocol0 = n0 + warp_n * 32;
#pragma unroll
    for (int ni = 0; ni < 4; ++ni) {
        const int ncol = ocol0 + ni * 8 + c2;
        const float b0 = bias[ncol], b1 = bias[ncol + 1];
#pragma unroll
        for (int mi = 0; mi < 4; ++mi) {
            const int mrow = orow0 + mi * 16 + r;
            float2 v0 = { acc[mi][ni][0] + b0, acc[mi][ni][1] + b1 };
            float2 v1 = { acc[mi][ni][2] + b0, acc[mi][ni][3] + b1 };
            *reinterpret_cast<float2*>(out + (size_t)mrow * NDIM + ncol)       = v0;
            *reinterpret_cast<float2*>(out + (size_t)(mrow + 8) * NDIM + ncol) = v1;
        }
    }
}

// ---------------- Launch ----------------
extern "C" void kernel_launch(void* const* d_in, const int* in_sizes, int n_in,
                              void* d_out, int out_size) {
    const float* x       = (const float*)d_in[0];
    const int*   qweight = (const int*)d_in[1];
    const float* scales  = (const float*)d_in[2];
    const int*   qzeros  = (const int*)d_in[3];
    const float* bias    = (const float*)d_in[4];
    float* out = (float*)d_out;

    const long long xsz = (long long)in_sizes[0];
    const int M = (int)(xsz / KDIM);          // 8192

    // 1) x -> fp16
    const long long n4 = xsz / 4;
    convert_x_kernel<<<(unsigned)((n4 + 255) / 256), 256>>>(x, n4);

    // 2) dequant W -> Wt[N][K] fp16
    dequant_kernel<<<dim3((NDIM + 255) / 256, KDIM / 8), 256>>>(qweight, scales, qzeros);

    // 3) GEMM
    const int SMEM_BYTES = 2 * STAGES * TILE_B;   // 81920
    cudaFuncSetAttribute(gemm_kernel, cudaFuncAttributeMaxDynamicSharedMemorySize, SMEM_BYTES);
    gemm_kernel<<<dim3(NDIM / BN, M / BM), 256, SMEM_BYTES>>>(bias, out);
}

// round 3
// speedup vs baseline: 1.0116x; 1.0116x over previous
#include <cuda_runtime.h>
#include <cuda_fp16.h>
#include <cstdint>
#include <cstddef>

#define KDIM 4096
#define NDIM 11008
#define MMAX 8192
#define BM 128
#define BN 256
#define BK 32
#define STAGES 4
#define ROWH (BK + 8)                 // padded SMEM row (40 halfs)
#define ATILE_B (BM * ROWH * 2)       // 10240 B
#define BTILE_B (BN * ROWH * 2)       // 20480 B

// Scratch (static device globals — no dynamic allocation allowed)
__device__ __half g_Xh[(size_t)MMAX * KDIM];   // x as fp16, [M, K]
__device__ __half g_Wt[(size_t)NDIM * KDIM];   // dequantized W, transposed: [N, K]

// ---------------- helpers ----------------
__device__ __forceinline__ uint32_t smem_u32(const void* p) {
    uint32_t a;
    asm("{ .reg .u64 t; cvta.to.shared.u64 t, %1; cvt.u32.u64 %0, t; }" : "=r"(a) : "l"(p));
    return a;
}

__device__ __forceinline__ void cp16(uint32_t sdst, const void* gsrc) {
    asm volatile("cp.async.cg.shared.global [%0], [%1], 16;" :: "r"(sdst), "l"(gsrc));
}

__device__ __forceinline__ void ldm_x4(uint32_t& r0, uint32_t& r1, uint32_t& r2, uint32_t& r3,
                                       uint32_t addr) {
    asm volatile("ldmatrix.sync.aligned.m8n8.x4.shared.b16 {%0,%1,%2,%3}, [%4];"
                 : "=r"(r0), "=r"(r1), "=r"(r2), "=r"(r3) : "r"(addr));
}

__device__ __forceinline__ void mma16816(float* c,
                                         uint32_t a0, uint32_t a1, uint32_t a2, uint32_t a3,
                                         uint32_t b0, uint32_t b1) {
    asm volatile("mma.sync.aligned.m16n8k16.row.col.f32.f16.f16.f32 "
                 "{%0,%1,%2,%3}, {%4,%5,%6,%7}, {%8,%9}, {%0,%1,%2,%3};"
                 : "+f"(c[0]), "+f"(c[1]), "+f"(c[2]), "+f"(c[3])
                 : "r"(a0), "r"(a1), "r"(a2), "r"(a3), "r"(b0), "r"(b1));
}

// ---------------- Kernel 1: x fp32 -> fp16 ----------------
__global__ void convert_x_kernel(const float* __restrict__ x, long long n4) {
    long long i = (long long)blockIdx.x * blockDim.x + threadIdx.x;
    if (i < n4) {
        float4 v = reinterpret_cast<const float4*>(x)[i];
        __half2 h0 = __floats2half2_rn(v.x, v.y);
        __half2 h1 = __floats2half2_rn(v.z, v.w);
        reinterpret_cast<__half2*>(g_Xh)[i * 2]     = h0;
        reinterpret_cast<__half2*>(g_Xh)[i * 2 + 1] = h1;
    }
}

// ---------------- Kernel 2: dequant -> Wt[N][K] fp16 (SMEM transpose tile) ----------------
// Tile: 64 n x 64 k per block, 256 threads. Coalesced reads AND coalesced 32B writes.
__global__ void __launch_bounds__(256)
dequant_kernel(const int* __restrict__ qweight,
               const float* __restrict__ scales,
               const int* __restrict__ qzeros) {
    __shared__ __half s[64][72];      // 64 rows (n) x 64 k + pad
    const int t  = threadIdx.x;
    const int n0 = blockIdx.x * 64;
    const int k0 = blockIdx.y * 64;
    const int g  = k0 >> 7;           // one quant group per tile (64 | k0, GROUP=128)

    const int nl = t & 63;
    const int n  = n0 + nl;
    const uint32_t zq = ((uint32_t)qzeros[(size_t)g * (NDIM / 8) + (n >> 3)] >> ((n & 7) * 4)) & 15u;
    const float z = (float)(zq + 1u);
    const float sc = scales[(size_t)g * NDIM + n];

#pragma unroll
    for (int p = 0; p < 2; ++p) {
        const int kpl = (t >> 6) + 4 * p;                     // 0..7 within tile
        const uint32_t qw = (uint32_t)qweight[(size_t)(k0 / 8 + kpl) * NDIM + n];
        union { uint4 u; __half h[8]; } v;
#pragma unroll
        for (int j = 0; j < 8; ++j) {
            float q = (float)((qw >> (4 * j)) & 15u);
            v.h[j] = __float2half_rn((q - z) * sc);
        }
        *reinterpret_cast<uint4*>(&s[nl][kpl * 8]) = v.u;
    }
    __syncthreads();

    const int rn = t >> 2, c = t & 3;                         // 32B per thread, row-contiguous
    uint4 v0 = *reinterpret_cast<const uint4*>(&s[rn][c * 16]);
    uint4 v1 = *reinterpret_cast<const uint4*>(&s[rn][c * 16 + 8]);
    __half* dst = &g_Wt[(size_t)(n0 + rn) * KDIM + k0 + c * 16];
    *reinterpret_cast<uint4*>(dst)     = v0;
    *reinterpret_cast<uint4*>(dst + 8) = v1;
}

// ---------------- Kernel 3: mma.sync fp16 GEMM ----------------
// CTA tile 128x256, BK=32, 256 threads = 8 warps (2m x 4n), warp tile 64x64, 4-stage cp.async.
__global__ void __launch_bounds__(256)
gemm_kernel(const float* __restrict__ bias, float* __restrict__ out) {
    extern __shared__ char dsm[];
    const uint32_t sbase = smem_u32(dsm);
    const uint32_t bbase = sbase + STAGES * ATILE_B;

    const int tid  = threadIdx.x;
    const int lane = tid & 31;
    const int wid  = tid >> 5;
    const int warp_m = wid & 1;       // 2 -> 64 rows each
    const int warp_n = wid >> 1;      // 4 -> 64 cols each

    // grouped CTA rasterization: wave works on ~12x12 tile block (L2-resident)
    const int PN = gridDim.x, PM = gridDim.y;
    const int bid = blockIdx.y * PN + blockIdx.x;
    const int GM = 12;
    const int npg = GM * PN;
    const int gid = bid / npg;
    const int fm  = gid * GM;
    const int gsm = (PM - fm < GM) ? (PM - fm) : GM;
    const int pm  = fm + (bid % gsm);
    const int pn  = (bid % npg) / gsm;
    const int m0 = pm * BM;
    const int n0 = pn * BN;

    const __half* Ag = g_Xh + (size_t)m0 * KDIM;
    const __half* Bg = g_Wt + (size_t)n0 * KDIM;

    const int lrow = tid >> 2;        // 0..63
    const int lchk = tid & 3;         // 16B chunk within 64B k-row

    float acc[4][8][4];
#pragma unroll
    for (int i = 0; i < 4; ++i)
#pragma unroll
        for (int j = 0; j < 8; ++j)
#pragma unroll
            for (int k = 0; k < 4; ++k) acc[i][j][k] = 0.f;

    // fragment SMEM coordinates
    const int a_r = warp_m * 64 + (lane & 15);
    const int a_c = (lane >> 4) * 8;
    // B x4 trick: one ldmatrix.x4 loads frags for two consecutive ni
    const int b_r = warp_n * 64 + ((lane >> 4) * 8) + (lane & 7);
    const int b_c = ((lane >> 3) & 1) * 8;

    const int NIT = KDIM / BK;        // 128

#pragma unroll
    for (int s = 0; s < STAGES - 1; ++s) {
        const int k0 = s * BK;
        const uint32_t sa  = sbase + s * ATILE_B;
        const uint32_t sbb = bbase + s * BTILE_B;
#pragma unroll
        for (int p = 0; p < 2; ++p) {
            const int row = lrow + p * 64;
            cp16(sa + (uint32_t)(row * ROWH + lchk * 8) * 2,
                 Ag + (size_t)row * KDIM + k0 + lchk * 8);
        }
#pragma unroll
        for (int p = 0; p < 4; ++p) {
            const int row = lrow + p * 64;
            cp16(sbb + (uint32_t)(row * ROWH + lchk * 8) * 2,
                 Bg + (size_t)row * KDIM + k0 + lchk * 8);
        }
        asm volatile("cp.async.commit_group;" ::: "memory");
    }

#pragma unroll 1
    for (int it = 0; it < NIT; ++it) {
        asm volatile("cp.async.wait_group 2;" ::: "memory");
        __syncthreads();

        const int nk = it + STAGES - 1;
        if (nk < NIT) {
            const int st = nk & (STAGES - 1);
            const int k0 = nk * BK;
            const uint32_t sa  = sbase + st * ATILE_B;
            const uint32_t sbb = bbase + st * BTILE_B;
#pragma unroll
            for (int p = 0; p < 2; ++p) {
                const int row = lrow + p * 64;
                cp16(sa + (uint32_t)(row * ROWH + lchk * 8) * 2,
                     Ag + (size_t)row * KDIM + k0 + lchk * 8);
            }
#pragma unroll
            for (int p = 0; p < 4; ++p) {
                const int row = lrow + p * 64;
                cp16(sbb + (uint32_t)(row * ROWH + lchk * 8) * 2,
                     Bg + (size_t)row * KDIM + k0 + lchk * 8);
            }
        }
        asm volatile("cp.async.commit_group;" ::: "memory");

        const int st = it & (STAGES - 1);
        const uint32_t sa  = sbase + st * ATILE_B;
        const uint32_t sbb = bbase + st * BTILE_B;
#pragma unroll
        for (int ks = 0; ks < 2; ++ks) {
            uint32_t Af[4][4], Bf[4][4];
#pragma unroll
            for (int mi = 0; mi < 4; ++mi)
                ldm_x4(Af[mi][0], Af[mi][1], Af[mi][2], Af[mi][3],
                       sa + (uint32_t)(((a_r + mi * 16) * ROWH) + ks * 16 + a_c) * 2);
#pragma unroll
            for (int nj = 0; nj < 4; ++nj)     // each covers ni = 2*nj, 2*nj+1
                ldm_x4(Bf[nj][0], Bf[nj][1], Bf[nj][2], Bf[nj][3],
                       sbb + (uint32_t)(((b_r + nj * 16) * ROWH) + ks * 16 + b_c) * 2);
#pragma unroll
            for (int mi = 0; mi < 4; ++mi)
#pragma unroll
                for (int nj = 0; nj < 4; ++nj) {
                    mma16816(acc[mi][2 * nj],
                             Af[mi][0], Af[mi][1], Af[mi][2], Af[mi][3],
                             Bf[nj][0], Bf[nj][1]);
                    mma16816(acc[mi][2 * nj + 1],
                             Af[mi][0], Af[mi][1], Af[mi][2], Af[mi][3],
                             Bf[nj][2], Bf[nj][3]);
                }
        }
    }
    asm volatile("cp.async.wait_group 0;" ::: "memory");

    // epilogue
    const int r  = lane >> 2;
    const int c2 = (lane & 3) * 2;
    const int orow0 = m0 + warp_m * 64;
    const int ocol0 = n0 + warp_n * 64;
#pragma unroll
    for (int ni = 0; ni < 8; ++ni) {
        const int ncol = ocol0 + ni * 8 + c2;
        const float b0 = bias[ncol], b1 = bias[ncol + 1];
#pragma unroll
        for (int mi = 0; mi < 4; ++mi) {
            const int mrow = orow0 + mi * 16 + r;
            float2 v0 = { acc[mi][ni][0] + b0, acc[mi][ni][1] + b1 };
            float2 v1 = { acc[mi][ni][2] + b0, acc[mi][ni][3] + b1 };
            *reinterpret_cast<float2*>(out + (size_t)mrow * NDIM + ncol)       = v0;
            *reinterpret_cast<float2*>(out + (size_t)(mrow + 8) * NDIM + ncol) = v1;
        }
    }
}

// ---------------- Launch ----------------
extern "C" void kernel_launch(void* const* d_in, const int* in_sizes, int n_in,
                              void* d_out, int out_size) {
    const float* x       = (const float*)d_in[0];
    const int*   qweight = (const int*)d_in[1];
    const float* scales  = (const float*)d_in[2];
    const int*   qzeros  = (const int*)d_in[3];
    const float* bias    = (const float*)d_in[4];
    float* out = (float*)d_out;

    const long long xsz = (long long)in_sizes[0];
    const int M = (int)(xsz / KDIM);          // 8192

    // 1) x -> fp16
    const long long n4 = xsz / 4;
    convert_x_kernel<<<(unsigned)((n4 + 255) / 256), 256>>>(x, n4);

    // 2) dequant W -> Wt[N][K] fp16
    dequant_kernel<<<dim3(NDIM / 64, KDIM / 64), 256>>>(qweight, scales, qzeros);

    // 3) GEMM
    const int SMEM_BYTES = STAGES * (ATILE_B + BTILE_B);   // 122880
    cudaFuncSetAttribute(gemm_kernel, cudaFuncAttributeMaxDynamicSharedMemorySize, SMEM_BYTES);
    gemm_kernel<<<dim3(NDIM / BN, M / BM), 256, SMEM_BYTES>>>(bias, out);
}